// round 2
// baseline (speedup 1.0000x reference)
#include <cuda_runtime.h>

#define N_NODES 50000
#define N_EDGES 1600000
#define D 128

// Scratch (allocation-free rule: __device__ globals)
__device__ float g_buf0[N_NODES * D];   // input features per hop (pre-scaled)
__device__ float g_buf1[N_NODES * D];   // aggregation accumulator
__device__ float g_deg[N_NODES];
__device__ float g_norm[N_NODES];

// ---------------------------------------------------------------------------
// Zero the accumulator and the degree array.
// ---------------------------------------------------------------------------
__global__ void k_zero_all() {
    int i = blockIdx.x * blockDim.x + threadIdx.x;
    const int total4 = N_NODES * D / 4;   // 1.6M float4
    if (i < total4) {
        ((float4*)g_buf1)[i] = make_float4(0.f, 0.f, 0.f, 0.f);
    }
    if (i < N_NODES) {
        g_deg[i] = 0.f;
    }
}

// ---------------------------------------------------------------------------
// Degree histogram: one thread per edge. Indices are int32 (JAX demotes
// int64 -> int32 without x64 mode).
// ---------------------------------------------------------------------------
__global__ void k_deg(const int* __restrict__ dst) {
    int e = blockIdx.x * blockDim.x + threadIdx.x;
    if (e < N_EDGES) {
        atomicAdd(&g_deg[dst[e]], 1.0f);
    }
}

// ---------------------------------------------------------------------------
// norm = clip(deg,1)^-0.5
// ---------------------------------------------------------------------------
__global__ void k_norm() {
    int i = blockIdx.x * blockDim.x + threadIdx.x;
    if (i < N_NODES) {
        float d = g_deg[i];
        g_norm[i] = rsqrtf(fmaxf(d, 1.0f));
    }
}

// ---------------------------------------------------------------------------
// buf0 = feat * norm[row]   (float4 vectorized; 32 float4 per row)
// ---------------------------------------------------------------------------
__global__ void k_scale0(const float* __restrict__ feat) {
    int idx = blockIdx.x * blockDim.x + threadIdx.x;
    const int total4 = N_NODES * D / 4;
    if (idx >= total4) return;
    int row = idx >> 5;                  // 128/4 = 32 float4 per row
    float nm = g_norm[row];
    float4 v = ((const float4*)feat)[idx];
    v.x *= nm; v.y *= nm; v.z *= nm; v.w *= nm;
    ((float4*)g_buf0)[idx] = v;
}

// ---------------------------------------------------------------------------
// Aggregation: warp per edge, lane moves one float4.
// buf1[dst] += buf0[src] via red.global.add.v4.f32 (L2-side vector reduction).
// ---------------------------------------------------------------------------
__global__ void k_agg(const int* __restrict__ src,
                      const int* __restrict__ dst) {
    int gw   = (blockIdx.x * blockDim.x + threadIdx.x) >> 5;
    int lane = threadIdx.x & 31;
    if (gw >= N_EDGES) return;
    int s = __ldg(&src[gw]);
    int d = __ldg(&dst[gw]);
    float4 v = __ldg(((const float4*)(g_buf0 + (size_t)s * D)) + lane);
    float* p = g_buf1 + (size_t)d * D + lane * 4;
    asm volatile("red.global.add.v4.f32 [%0], {%1,%2,%3,%4};"
                 :: "l"(p), "f"(v.x), "f"(v.y), "f"(v.z), "f"(v.w)
                 : "memory");
}

// ---------------------------------------------------------------------------
// Between hops: buf0 = buf1 * norm^2 (post-hop1 norm * pre-hop2 norm),
// and re-zero buf1 for the second aggregation.
// ---------------------------------------------------------------------------
__global__ void k_mid() {
    int idx = blockIdx.x * blockDim.x + threadIdx.x;
    const int total4 = N_NODES * D / 4;
    if (idx >= total4) return;
    int row = idx >> 5;
    float nm = g_norm[row];
    float s = nm * nm;
    float4 v = ((float4*)g_buf1)[idx];
    v.x *= s; v.y *= s; v.z *= s; v.w *= s;
    ((float4*)g_buf0)[idx] = v;
    ((float4*)g_buf1)[idx] = make_float4(0.f, 0.f, 0.f, 0.f);
}

// ---------------------------------------------------------------------------
// GEMM: out[n][o] = sum_k (buf1[n][k] * norm[n]) * W[o][k] + b[o]
// Block tile: 64 rows x 128 cols, k-chunks of 32.
// 256 threads, each computes 4 rows x 8 cols (strided cols: tx + 16*j).
// Smem padded (+1) for conflict-free transposed stores and reads.
// ---------------------------------------------------------------------------
#define BM 64
#define BK 32
__global__ void __launch_bounds__(256) k_gemm(const float* __restrict__ W,
                                              const float* __restrict__ bias,
                                              float* __restrict__ out) {
    __shared__ float As[BK][BM + 1];   // [k][row]
    __shared__ float Bs[BK][D + 1];    // [k][col]

    int t  = threadIdx.x;       // 0..255
    int tx = t & 15;            // col lane: cols tx + 16*j
    int ty = t >> 4;            // row group: rows ty*4 + i
    int row0 = blockIdx.x * BM;

    float acc[4][8];
#pragma unroll
    for (int i = 0; i < 4; i++)
#pragma unroll
        for (int j = 0; j < 8; j++) acc[i][j] = 0.f;

    for (int k0 = 0; k0 < D; k0 += BK) {
        // A tile: 64x32 = 2048 elems, 8 per thread. Coalesced global read,
        // transposed smem store (stride BM+1=65 -> conflict-free).
#pragma unroll
        for (int i = 0; i < 8; i++) {
            int idx = t + i * 256;
            int r  = idx >> 5;     // 0..63
            int kk = idx & 31;
            int rg = row0 + r;
            float v = 0.f;
            if (rg < N_NODES) v = g_buf1[(size_t)rg * D + k0 + kk] * g_norm[rg];
            As[kk][r] = v;
        }
        // B tile: 32x128 = 4096 elems, 16 per thread. W is [o][k] row-major.
#pragma unroll
        for (int i = 0; i < 16; i++) {
            int idx = t + i * 256;
            int o  = idx >> 5;     // 0..127
            int kk = idx & 31;
            Bs[kk][o] = W[o * D + k0 + kk];
        }
        __syncthreads();

#pragma unroll
        for (int kk = 0; kk < BK; kk++) {
            float a[4], bv[8];
#pragma unroll
            for (int i = 0; i < 4; i++) a[i] = As[kk][ty * 4 + i];
#pragma unroll
            for (int j = 0; j < 8; j++) bv[j] = Bs[kk][tx + 16 * j];
#pragma unroll
            for (int i = 0; i < 4; i++)
#pragma unroll
                for (int j = 0; j < 8; j++) acc[i][j] += a[i] * bv[j];
        }
        __syncthreads();
    }

#pragma unroll
    for (int i = 0; i < 4; i++) {
        int rg = row0 + ty * 4 + i;
        if (rg >= N_NODES) continue;
#pragma unroll
        for (int j = 0; j < 8; j++) {
            int c = tx + 16 * j;
            out[(size_t)rg * D + c] = acc[i][j] + bias[c];
        }
    }
}

// ---------------------------------------------------------------------------
// kernel_launch
// Inputs (metadata order): feat f32[50000*128], src i32[1.6M], dst i32[1.6M],
//                          W f32[128*128], b f32[128]. Output f32[50000*128].
// ---------------------------------------------------------------------------
extern "C" void kernel_launch(void* const* d_in, const int* in_sizes, int n_in,
                              void* d_out, int out_size) {
    const float* feat = (const float*)d_in[0];
    const int*   src  = (const int*)d_in[1];
    const int*   dst  = (const int*)d_in[2];
    const float* W    = (const float*)d_in[3];
    const float* bias = (const float*)d_in[4];
    float*       out  = (float*)d_out;

    const int total4 = N_NODES * D / 4;                    // 1,600,000
    const int gElem  = (total4 + 255) / 256;               // elementwise grids
    const int gEdge  = (N_EDGES + 255) / 256;              // 1 thread / edge
    const int gAggW  = (N_EDGES * 32 + 255) / 256;         // 1 warp / edge
    const int gNode  = (N_NODES + 255) / 256;
    const int gGemm  = (N_NODES + BM - 1) / BM;            // 782

    k_zero_all<<<gElem, 256>>>();
    k_deg<<<gEdge, 256>>>(dst);
    k_norm<<<gNode, 256>>>();
    k_scale0<<<gElem, 256>>>(feat);
    k_agg<<<gAggW, 256>>>(src, dst);          // hop 1: buf0 -> buf1
    k_mid<<<gElem, 256>>>();                  // buf0 = buf1*norm^2; buf1 = 0
    k_agg<<<gAggW, 256>>>(src, dst);          // hop 2: buf0 -> buf1
    k_gemm<<<gGemm, 256>>>(W, bias, out);     // out = (buf1*norm) @ W^T + b
}

// round 4
// speedup vs baseline: 2.1549x; 2.1549x over previous
#include <cuda_runtime.h>

#define N_NODES 50000
#define N_EDGES 1600000
#define D 128

#define SCAN_B 1024
#define SCAN_NBLK ((N_NODES + SCAN_B - 1) / SCAN_B)   // 49

// Scratch (allocation-free rule: __device__ globals)
__device__ float g_buf0[N_NODES * D];
__device__ float g_buf1[N_NODES * D];
__device__ int   g_cnt[N_NODES];          // in-degree histogram
__device__ int   g_cur[N_NODES];          // CSR fill cursors
__device__ int   g_rowptr[N_NODES + 1];
__device__ int   g_csr_src[N_EDGES];
__device__ float g_norm[N_NODES];
__device__ int   g_blocksum[SCAN_NBLK];
__device__ int   g_blockoff[SCAN_NBLK];

// ---------------------------------------------------------------------------
// Zero counters + cursors.
// ---------------------------------------------------------------------------
__global__ void k_zero() {
    int i = blockIdx.x * blockDim.x + threadIdx.x;
    if (i < N_NODES) { g_cnt[i] = 0; g_cur[i] = 0; }
}

// ---------------------------------------------------------------------------
// In-degree histogram (int atomics).
// ---------------------------------------------------------------------------
__global__ void k_deg(const int* __restrict__ dst) {
    int e = blockIdx.x * blockDim.x + threadIdx.x;
    if (e < N_EDGES) atomicAdd(&g_cnt[dst[e]], 1);
}

// ---------------------------------------------------------------------------
// Scan pass 1: per-block exclusive scan of g_cnt into g_rowptr, block totals.
// ---------------------------------------------------------------------------
__global__ void __launch_bounds__(SCAN_B) k_scan1() {
    __shared__ int sh[SCAN_B];
    int i = blockIdx.x * SCAN_B + threadIdx.x;
    int v = (i < N_NODES) ? g_cnt[i] : 0;
    sh[threadIdx.x] = v;
    __syncthreads();
#pragma unroll
    for (int off = 1; off < SCAN_B; off <<= 1) {
        int t = (threadIdx.x >= off) ? sh[threadIdx.x - off] : 0;
        __syncthreads();
        sh[threadIdx.x] += t;
        __syncthreads();
    }
    if (i < N_NODES) g_rowptr[i] = sh[threadIdx.x] - v;  // exclusive, local
    if (threadIdx.x == SCAN_B - 1) g_blocksum[blockIdx.x] = sh[SCAN_B - 1];
}

// ---------------------------------------------------------------------------
// Scan pass 2: serial exclusive scan of 49 block sums (trivial size).
// ---------------------------------------------------------------------------
__global__ void k_scan2() {
    if (threadIdx.x == 0 && blockIdx.x == 0) {
        int acc = 0;
        for (int b = 0; b < SCAN_NBLK; b++) {
            g_blockoff[b] = acc;
            acc += g_blocksum[b];
        }
    }
}

// ---------------------------------------------------------------------------
// Scan pass 3: add block offsets; also compute norm; close rowptr.
// ---------------------------------------------------------------------------
__global__ void __launch_bounds__(SCAN_B) k_scan3() {
    int i = blockIdx.x * SCAN_B + threadIdx.x;
    if (i < N_NODES) {
        g_rowptr[i] += g_blockoff[blockIdx.x];
        g_norm[i] = rsqrtf(fmaxf((float)g_cnt[i], 1.0f));
    }
    if (i == 0) g_rowptr[N_NODES] = N_EDGES;
}

// ---------------------------------------------------------------------------
// CSR fill: scatter src indices into per-dst contiguous lists.
// ---------------------------------------------------------------------------
__global__ void k_fill(const int* __restrict__ src,
                       const int* __restrict__ dst) {
    int e = blockIdx.x * blockDim.x + threadIdx.x;
    if (e < N_EDGES) {
        int d = dst[e];
        int p = atomicAdd(&g_cur[d], 1);
        g_csr_src[g_rowptr[d] + p] = src[e];
    }
}

// ---------------------------------------------------------------------------
// Pull-mode hop: warp per dst node.
//   out[d] = norm[d] * sum_{s in N(d)} norm[s] * in[s]
// Lane carries one float4 (32 lanes * 4 = 128 cols). No atomics.
// HOP=1: in = feat (kernel arg), out = g_buf0 (device symbol, bound in device code)
// HOP=2: in = g_buf0,            out = g_buf1
// ---------------------------------------------------------------------------
template <int HOP>
__global__ void __launch_bounds__(256) k_hop(const float* __restrict__ feat) {
    int w    = (blockIdx.x * blockDim.x + threadIdx.x) >> 5;
    int lane = threadIdx.x & 31;
    if (w >= N_NODES) return;

    const float* in  = (HOP == 1) ? feat   : g_buf0;
    float*       out = (HOP == 1) ? g_buf0 : g_buf1;

    int beg = g_rowptr[w];
    int end = g_rowptr[w + 1];
    float4 acc = make_float4(0.f, 0.f, 0.f, 0.f);
    const float4* in4 = (const float4*)in;
    int e = beg;
    // unroll by 4 for MLP on the gathers
    for (; e + 4 <= end; e += 4) {
        int s0 = g_csr_src[e + 0], s1 = g_csr_src[e + 1];
        int s2 = g_csr_src[e + 2], s3 = g_csr_src[e + 3];
        float n0 = g_norm[s0], n1 = g_norm[s1], n2 = g_norm[s2], n3 = g_norm[s3];
        float4 v0 = __ldg(in4 + s0 * 32 + lane);
        float4 v1 = __ldg(in4 + s1 * 32 + lane);
        float4 v2 = __ldg(in4 + s2 * 32 + lane);
        float4 v3 = __ldg(in4 + s3 * 32 + lane);
        acc.x += n0 * v0.x + n1 * v1.x + n2 * v2.x + n3 * v3.x;
        acc.y += n0 * v0.y + n1 * v1.y + n2 * v2.y + n3 * v3.y;
        acc.z += n0 * v0.z + n1 * v1.z + n2 * v2.z + n3 * v3.z;
        acc.w += n0 * v0.w + n1 * v1.w + n2 * v2.w + n3 * v3.w;
    }
    for (; e < end; e++) {
        int s = g_csr_src[e];
        float ns = g_norm[s];
        float4 v = __ldg(in4 + s * 32 + lane);
        acc.x += ns * v.x; acc.y += ns * v.y;
        acc.z += ns * v.z; acc.w += ns * v.w;
    }
    float nd = g_norm[w];
    acc.x *= nd; acc.y *= nd; acc.z *= nd; acc.w *= nd;
    ((float4*)out)[w * 32 + lane] = acc;
}

// ---------------------------------------------------------------------------
// GEMM: out[n][o] = sum_k buf1[n][k] * W[o][k] + b[o]  (buf1 pre-normalized)
// ---------------------------------------------------------------------------
#define BM 64
#define BK 32
__global__ void __launch_bounds__(256) k_gemm(const float* __restrict__ W,
                                              const float* __restrict__ bias,
                                              float* __restrict__ out) {
    __shared__ float As[BK][BM + 1];
    __shared__ float Bs[BK][D + 1];

    int t  = threadIdx.x;
    int tx = t & 15;
    int ty = t >> 4;
    int row0 = blockIdx.x * BM;

    float acc[4][8];
#pragma unroll
    for (int i = 0; i < 4; i++)
#pragma unroll
        for (int j = 0; j < 8; j++) acc[i][j] = 0.f;

    for (int k0 = 0; k0 < D; k0 += BK) {
#pragma unroll
        for (int i = 0; i < 8; i++) {
            int idx = t + i * 256;
            int r  = idx >> 5;
            int kk = idx & 31;
            int rg = row0 + r;
            float v = 0.f;
            if (rg < N_NODES) v = g_buf1[(size_t)rg * D + k0 + kk];
            As[kk][r] = v;
        }
#pragma unroll
        for (int i = 0; i < 16; i++) {
            int idx = t + i * 256;
            int o  = idx >> 5;
            int kk = idx & 31;
            Bs[kk][o] = W[o * D + k0 + kk];
        }
        __syncthreads();

#pragma unroll
        for (int kk = 0; kk < BK; kk++) {
            float a[4], bv[8];
#pragma unroll
            for (int i = 0; i < 4; i++) a[i] = As[kk][ty * 4 + i];
#pragma unroll
            for (int j = 0; j < 8; j++) bv[j] = Bs[kk][tx + 16 * j];
#pragma unroll
            for (int i = 0; i < 4; i++)
#pragma unroll
                for (int j = 0; j < 8; j++) acc[i][j] += a[i] * bv[j];
        }
        __syncthreads();
    }

#pragma unroll
    for (int i = 0; i < 4; i++) {
        int rg = row0 + ty * 4 + i;
        if (rg >= N_NODES) continue;
#pragma unroll
        for (int j = 0; j < 8; j++) {
            int c = tx + 16 * j;
            out[(size_t)rg * D + c] = acc[i][j] + bias[c];
        }
    }
}

// ---------------------------------------------------------------------------
// kernel_launch
// ---------------------------------------------------------------------------
extern "C" void kernel_launch(void* const* d_in, const int* in_sizes, int n_in,
                              void* d_out, int out_size) {
    const float* feat = (const float*)d_in[0];
    const int*   src  = (const int*)d_in[1];
    const int*   dst  = (const int*)d_in[2];
    const float* W    = (const float*)d_in[3];
    const float* bias = (const float*)d_in[4];
    float*       out  = (float*)d_out;

    const int gNode = (N_NODES + 255) / 256;
    const int gEdge = (N_EDGES + 255) / 256;
    const int gHop  = (N_NODES * 32 + 255) / 256;   // warp per node
    const int gGemm = (N_NODES + BM - 1) / BM;

    k_zero <<<gNode, 256>>>();
    k_deg  <<<gEdge, 256>>>(dst);
    k_scan1<<<SCAN_NBLK, SCAN_B>>>();
    k_scan2<<<1, 32>>>();
    k_scan3<<<SCAN_NBLK, SCAN_B>>>();
    k_fill <<<gEdge, 256>>>(src, dst);
    k_hop<1><<<gHop, 256>>>(feat);    // feat   -> g_buf0
    k_hop<2><<<gHop, 256>>>(feat);    // g_buf0 -> g_buf1
    k_gemm <<<gGemm, 256>>>(W, bias, out);
}